// round 9
// baseline (speedup 1.0000x reference)
#include <cuda_runtime.h>

#define NSTEPS 2048
#define D      128
#define NTHR   512

// One persistent CTA. Thread t owns row r=t>>2, columns [c0, c0+32) of each
// 128x128 matrix (J, SqqSum, SqvSum), all register-resident.
__global__ __launch_bounds__(NTHR, 1)
void gim_kernel(const float* __restrict__ gq,
                const float* __restrict__ gk,
                const float* __restrict__ gv,
                float* __restrict__ out, int out_size)
{
    __shared__ __align__(16) float sq[2][D];
    __shared__ __align__(16) float sk[2][D];
    __shared__ __align__(16) float sv[2][D];
    __shared__ __align__(16) float su[D];
    __shared__ __align__(16) float sg[D];
    __shared__ __align__(16) float sw[D];
    __shared__ __align__(16) float sh[D];
    __shared__ float  sred[24];     // 4 warps x 6 partial dots
    __shared__ float  s_wf, s_wi;
    __shared__ int    s_mode;
    __shared__ double sZ, sA, sTr;  // running trace accumulators (thread 0 only)

    const int t    = threadIdx.x;
    const int r    = t >> 2;          // row 0..127
    const int c0   = (t & 3) << 5;    // column base 0,32,64,96
    const int lane = t & 31;

    float J_[32], Cqq[32], Cqv[32];
    #pragma unroll
    for (int i = 0; i < 32; i++) { J_[i] = 0.f; Cqq[i] = 0.f; Cqv[i] = 0.f; }

    if (t == 0) { sZ = 0.0; sA = 0.0; sTr = 0.0; }

    // stage step-0 q,k,v
    if (t < 96) {
        const int vec = t >> 5, j = t & 31;
        const float* src = (vec == 0) ? gq : (vec == 1) ? gk : gv;
        float4 x = *(const float4*)&src[j * 4];
        float* dst = (vec == 0) ? sq[0] : (vec == 1) ? sk[0] : sv[0];
        *(float4*)&dst[j * 4] = x;
    }
    __syncthreads();

    float* outc = out;
    float* outu = (out_size >= 2 * NSTEPS) ? (out + NSTEPS) : (float*)0;
    float* outJ = (out_size >= 2 * NSTEPS + D * D) ? (out + 2 * NSTEPS) : (float*)0;

    for (int l0 = 0; l0 < NSTEPS; l0++) {
        const int buf = l0 & 1;
        const float* q = sq[buf];
        const float* k = sk[buf];
        const float* v = sv[buf];

        // prefetch next step's q,k,v into registers (hidden under compute)
        float4 pf = make_float4(0.f, 0.f, 0.f, 0.f);
        bool havePf = false;
        if (t < 96 && (l0 + 1) < NSTEPS) {
            const int vec = t >> 5, j = t & 31;
            const float* src = (vec == 0) ? gq : (vec == 1) ? gk : gv;
            pf = *(const float4*)&src[(l0 + 1) * D + j * 4];
            havePf = true;
        }

        // ---- Phase A: u = J_old q ; SqqS += q q^T ; SqvS += q v^T ;
        //              g = SqqS_new k ; w = SqvS_new v  (one fused sweep)
        const float qr = q[r];
        float pu = 0.f, pg = 0.f, pw = 0.f;
        #pragma unroll
        for (int i = 0; i < 32; i += 4) {
            float4 qc = *(const float4*)&q[c0 + i];
            float4 vc = *(const float4*)&v[c0 + i];
            float4 kc = *(const float4*)&k[c0 + i];
            pu += J_[i]*qc.x + J_[i+1]*qc.y + J_[i+2]*qc.z + J_[i+3]*qc.w;
            Cqq[i]   += qr * qc.x;  Cqq[i+1] += qr * qc.y;
            Cqq[i+2] += qr * qc.z;  Cqq[i+3] += qr * qc.w;
            Cqv[i]   += qr * vc.x;  Cqv[i+1] += qr * vc.y;
            Cqv[i+2] += qr * vc.z;  Cqv[i+3] += qr * vc.w;
            pg += Cqq[i]*kc.x + Cqq[i+1]*kc.y + Cqq[i+2]*kc.z + Cqq[i+3]*kc.w;
            pw += Cqv[i]*vc.x + Cqv[i+1]*vc.y + Cqv[i+2]*vc.z + Cqv[i+3]*vc.w;
        }
        pu += __shfl_xor_sync(0xffffffffu, pu, 1);
        pu += __shfl_xor_sync(0xffffffffu, pu, 2);
        pg += __shfl_xor_sync(0xffffffffu, pg, 1);
        pg += __shfl_xor_sync(0xffffffffu, pg, 2);
        pw += __shfl_xor_sync(0xffffffffu, pw, 1);
        pw += __shfl_xor_sync(0xffffffffu, pw, 2);
        if ((t & 3) == 0) { su[r] = pu; sg[r] = pg; sw[r] = pw; }
        __syncthreads();

        // ---- Phase B: h = J_old g
        float ph = 0.f;
        #pragma unroll
        for (int i = 0; i < 32; i += 4) {
            float4 gc = *(const float4*)&sg[c0 + i];
            ph += J_[i]*gc.x + J_[i+1]*gc.y + J_[i+2]*gc.z + J_[i+3]*gc.w;
        }
        ph += __shfl_xor_sync(0xffffffffu, ph, 1);
        ph += __shfl_xor_sync(0xffffffffu, ph, 2);
        if ((t & 3) == 0) sh[r] = ph;
        __syncthreads();

        // ---- Phase C1: six 128-length dots (warps 0..3)
        if (t < D) {
            float ui = su[t], gi = sg[t], wi_ = sw[t], hi = sh[t];
            float vi = v[t], ki = k[t];
            float d0 = ui * ui;   // ||u||^2
            float d1 = vi * ui;   // v.u
            float d2 = ki * gi;   // k.g
            float d3 = ki * wi_;  // k.w
            float d4 = vi * vi;   // v.v
            float d5 = vi * hi;   // v.h
            #pragma unroll
            for (int o = 16; o >= 1; o >>= 1) {
                d0 += __shfl_xor_sync(0xffffffffu, d0, o);
                d1 += __shfl_xor_sync(0xffffffffu, d1, o);
                d2 += __shfl_xor_sync(0xffffffffu, d2, o);
                d3 += __shfl_xor_sync(0xffffffffu, d3, o);
                d4 += __shfl_xor_sync(0xffffffffu, d4, o);
                d5 += __shfl_xor_sync(0xffffffffu, d5, o);
            }
            if (lane == 0) {
                const int w = t >> 5;
                sred[w*6+0] = d0; sred[w*6+1] = d1; sred[w*6+2] = d2;
                sred[w*6+3] = d3; sred[w*6+4] = d4; sred[w*6+5] = d5;
            }
        }
        __syncthreads();

        // ---- Phase C2: scalar logic (thread 0, double precision)
        if (t == 0) {
            double nu = 0, vu = 0, kg = 0, kw = 0, vvd = 0, vh = 0;
            #pragma unroll
            for (int w = 0; w < 4; w++) {
                nu  += (double)sred[w*6+0];
                vu  += (double)sred[w*6+1];
                kg  += (double)sred[w*6+2];
                kw  += (double)sred[w*6+3];
                vvd += (double)sred[w*6+4];
                vh  += (double)sred[w*6+5];
            }
            const int l = l0 + 1;
            const double linv = 1.0 / (double)l;
            // correlation update effect on running traces (J still old)
            const double Zc = sZ + vu;   // tr(J SqvS)
            const double Ac = sA + nu;   // tr(J SqqS J^T)
            const double sJ  = Zc * linv;
            const double sl  = kw * linv;
            const double AJJ = Ac * linv;
            const double All = vvd * (kg * linv);
            const double AJl = vh * linv;
            const bool first = (l == 1);
            const double AJJs   = (first || AJJ == 0.0) ? 1.0 : AJJ;
            const double Alls   = (first || All == 0.0) ? 1.0 : All;
            const double denom  = AJJ * All - AJl * AJl;
            const double denoms = (first || denom == 0.0) ? 1.0 : denom;
            const double margin = sl - AJl * (sJ / AJJs);
            const double wf = (All * sJ - AJl * sl) / denoms;
            const double wi = (AJJ * sl - AJl * sJ) / denoms;
            const double wfc = (wi <= 0.0) ? (sJ / AJJs) : ((wf <= 0.0) ? 0.0 : wf);
            const double wic = (wi <= 0.0) ? 0.0 : ((wf <= 0.0) ? (sl / Alls) : wi);
            const bool do_update = (margin > 0.0);

            int mode; double uwf = 1.0, uwi = 0.0;
            if (first)          { mode = 2; }
            else if (do_update) { mode = 1; uwf = wfc; uwi = wic; }
            else                { mode = 0; }

            sTr += vvd;
            double Zn, An;
            if (mode == 2)      { Zn = kw;                 An = vvd * kg; }
            else if (mode == 1) { Zn = uwf * Zc + uwi * kw;
                                  An = uwf*uwf*Ac + 2.0*uwf*uwi*vh + uwi*uwi*(vvd*kg); }
            else                { Zn = Zc; An = Ac; }
            sZ = Zn; sA = An;

            const double cost = (0.5 * sTr - Zn + 0.5 * An) * linv;
            outc[l0] = (float)cost;
            if (outu) outu[l0] = (first || do_update) ? 1.0f : 0.0f;
            s_mode = mode; s_wf = (float)uwf; s_wi = (float)uwi;
        }
        __syncthreads();

        // ---- Phase D: conditional J update
        const int mode = s_mode;
        if (mode) {
            const float vr = v[r];
            if (mode == 2) {
                #pragma unroll
                for (int i = 0; i < 32; i += 4) {
                    float4 kc = *(const float4*)&k[c0 + i];
                    J_[i]   = vr * kc.x; J_[i+1] = vr * kc.y;
                    J_[i+2] = vr * kc.z; J_[i+3] = vr * kc.w;
                }
            } else {
                const float wf = s_wf;
                const float a  = s_wi * vr;
                #pragma unroll
                for (int i = 0; i < 32; i += 4) {
                    float4 kc = *(const float4*)&k[c0 + i];
                    J_[i]   = wf * J_[i]   + a * kc.x;
                    J_[i+1] = wf * J_[i+1] + a * kc.y;
                    J_[i+2] = wf * J_[i+2] + a * kc.z;
                    J_[i+3] = wf * J_[i+3] + a * kc.w;
                }
            }
        }

        // commit prefetched next-step q,k,v
        if (havePf) {
            const int vec = t >> 5, j = t & 31, nb = buf ^ 1;
            float* dst = (vec == 0) ? sq[nb] : (vec == 1) ? sk[nb] : sv[nb];
            *(float4*)&dst[j * 4] = pf;
        }
        __syncthreads();
    }

    // ---- Final: write J
    if (outJ) {
        #pragma unroll
        for (int i = 0; i < 32; i += 4) {
            *(float4*)&outJ[r * D + c0 + i] =
                make_float4(J_[i], J_[i+1], J_[i+2], J_[i+3]);
        }
    }
}

extern "C" void kernel_launch(void* const* d_in, const int* in_sizes, int n_in,
                              void* d_out, int out_size)
{
    const float* q = (const float*)d_in[0];
    const float* k = (const float*)d_in[1];
    const float* v = (const float*)d_in[2];
    gim_kernel<<<1, NTHR>>>(q, k, v, (float*)d_out, out_size);
}

// round 14
// speedup vs baseline: 1.5564x; 1.5564x over previous
#include <cuda_runtime.h>

#define NSTEPS 2048
#define D      128
#define NTHR   512

typedef unsigned long long u64;

// ---- packed fp32x2 helpers (sm_103a) -------------------------------------
__device__ __forceinline__ u64 ffma2(u64 a, u64 b, u64 c) {
    u64 d; asm("fma.rn.f32x2 %0, %1, %2, %3;" : "=l"(d) : "l"(a), "l"(b), "l"(c));
    return d;
}
__device__ __forceinline__ u64 fmul2(u64 a, u64 b) {
    u64 d; asm("mul.rn.f32x2 %0, %1, %2;" : "=l"(d) : "l"(a), "l"(b));
    return d;
}
__device__ __forceinline__ u64 pack2(float x) {
    u64 r; asm("mov.b64 %0, {%1, %1};" : "=l"(r) : "f"(x));
    return r;
}
__device__ __forceinline__ float hadd2(u64 x) {
    float lo, hi; asm("mov.b64 {%0, %1}, %2;" : "=f"(lo), "=f"(hi) : "l"(x));
    return lo + hi;
}

// One persistent CTA. Thread t owns row r=t>>2, columns [c0, c0+32) of each
// 128x128 matrix (J, SqqSum, SqvSum) as 16 packed f32x2 registers per matrix.
__global__ __launch_bounds__(NTHR, 1)
void gim_kernel(const float* __restrict__ gq,
                const float* __restrict__ gk,
                const float* __restrict__ gv,
                float* __restrict__ out, int out_size)
{
    __shared__ __align__(16) float sq[2][D], sk[2][D], sv[2][D];
    __shared__ __align__(16) float su[D], sg[D], sw[D], sh[D];
    __shared__ float  s_wf, s_wi;
    __shared__ int    s_mode;
    __shared__ double sZd, sAd, sTd;   // running trace accumulators

    const int t  = threadIdx.x;
    const int r  = t >> 2;          // row 0..127
    const int c0 = (t & 3) << 5;    // column base 0,32,64,96

    u64 J2[16], Cqq2[16], Cqv2[16];
    #pragma unroll
    for (int i = 0; i < 16; i++) { J2[i] = 0ull; Cqq2[i] = 0ull; Cqv2[i] = 0ull; }

    if (t == 0) { sZd = 0.0; sAd = 0.0; sTd = 0.0; }

    // stage step-0 q,k,v
    if (t >= 32 && t < 128) {
        const int vec = (t - 32) >> 5, j = t & 31;
        const float* src = (vec == 0) ? gq : (vec == 1) ? gk : gv;
        float4 x = *(const float4*)&src[j * 4];
        float* dst = (vec == 0) ? sq[0] : (vec == 1) ? sk[0] : sv[0];
        *(float4*)&dst[j * 4] = x;
    }
    __syncthreads();

    float* outc = out;
    float* outu = (out_size >= 2 * NSTEPS) ? (out + NSTEPS) : (float*)0;
    float* outJ = (out_size >= 2 * NSTEPS + D * D) ? (out + 2 * NSTEPS) : (float*)0;

    for (int l0 = 0; l0 < NSTEPS; l0++) {
        const int buf = l0 & 1;
        const float* q = sq[buf];
        const float* k = sk[buf];
        const float* v = sv[buf];

        // async prefetch of next step's q,k,v straight into the other smem
        // buffer (no registers consumed); completes before the post-C barrier
        const bool havePf = (t >= 32 && t < 128 && (l0 + 1) < NSTEPS);
        if (havePf) {
            const int vec = (t - 32) >> 5, j = t & 31, nb = buf ^ 1;
            const float* src = (vec == 0) ? gq : (vec == 1) ? gk : gv;
            float* dst = ((vec == 0) ? sq[nb] : (vec == 1) ? sk[nb] : sv[nb]) + j * 4;
            unsigned sa = (unsigned)__cvta_generic_to_shared(dst);
            asm volatile("cp.async.ca.shared.global [%0], [%1], 16;\n\t"
                         "cp.async.commit_group;"
                         :: "r"(sa), "l"(&src[(l0 + 1) * D + j * 4]) : "memory");
        }

        // ---- Phase A (packed): u = J_old q ; SqqS += q q^T ; SqvS += q v^T ;
        //                        g = SqqS_new k ; w = SqvS_new v
        const u64 qr2 = pack2(q[r]);
        u64 pu2 = 0ull, pg2 = 0ull, pw2 = 0ull;
        #pragma unroll
        for (int j = 0; j < 8; j++) {
            ulonglong2 qc = *(const ulonglong2*)&q[c0 + 4 * j];
            ulonglong2 vc = *(const ulonglong2*)&v[c0 + 4 * j];
            ulonglong2 kc = *(const ulonglong2*)&k[c0 + 4 * j];
            pu2 = ffma2(J2[2*j],   qc.x, pu2);
            pu2 = ffma2(J2[2*j+1], qc.y, pu2);
            Cqq2[2*j]   = ffma2(qr2, qc.x, Cqq2[2*j]);
            Cqq2[2*j+1] = ffma2(qr2, qc.y, Cqq2[2*j+1]);
            Cqv2[2*j]   = ffma2(qr2, vc.x, Cqv2[2*j]);
            Cqv2[2*j+1] = ffma2(qr2, vc.y, Cqv2[2*j+1]);
            pg2 = ffma2(Cqq2[2*j],   kc.x, pg2);
            pg2 = ffma2(Cqq2[2*j+1], kc.y, pg2);
            pw2 = ffma2(Cqv2[2*j],   vc.x, pw2);
            pw2 = ffma2(Cqv2[2*j+1], vc.y, pw2);
        }
        float pu = hadd2(pu2), pg = hadd2(pg2), pw = hadd2(pw2);
        pu += __shfl_xor_sync(~0u, pu, 1);  pu += __shfl_xor_sync(~0u, pu, 2);
        pg += __shfl_xor_sync(~0u, pg, 1);  pg += __shfl_xor_sync(~0u, pg, 2);
        pw += __shfl_xor_sync(~0u, pw, 1);  pw += __shfl_xor_sync(~0u, pw, 2);
        if ((t & 3) == 0) { su[r] = pu; sg[r] = pg; sw[r] = pw; }
        __syncthreads();                                    // bar 1

        // ---- Phase B (packed): h = J_old g
        u64 ph2 = 0ull;
        #pragma unroll
        for (int j = 0; j < 8; j++) {
            ulonglong2 gc = *(const ulonglong2*)&sg[c0 + 4 * j];
            ph2 = ffma2(J2[2*j],   gc.x, ph2);
            ph2 = ffma2(J2[2*j+1], gc.y, ph2);
        }
        float ph = hadd2(ph2);
        ph += __shfl_xor_sync(~0u, ph, 1);  ph += __shfl_xor_sync(~0u, ph, 2);
        if ((t & 3) == 0) sh[r] = ph;
        __syncthreads();                                    // bar 2

        // ---- Phase C: warp 0 does the six 128-dots + scalar logic
        if (t < 32) {
            const int e = t << 2;
            float4 u4 = *(const float4*)&su[e];
            float4 g4 = *(const float4*)&sg[e];
            float4 w4 = *(const float4*)&sw[e];
            float4 h4 = *(const float4*)&sh[e];
            float4 v4 = *(const float4*)&v[e];
            float4 k4 = *(const float4*)&k[e];
            float nu = u4.x*u4.x + u4.y*u4.y + u4.z*u4.z + u4.w*u4.w;
            float vu = v4.x*u4.x + v4.y*u4.y + v4.z*u4.z + v4.w*u4.w;
            float kg = k4.x*g4.x + k4.y*g4.y + k4.z*g4.z + k4.w*g4.w;
            float kw = k4.x*w4.x + k4.y*w4.y + k4.z*w4.z + k4.w*w4.w;
            float vv = v4.x*v4.x + v4.y*v4.y + v4.z*v4.z + v4.w*v4.w;
            float vh = v4.x*h4.x + v4.y*h4.y + v4.z*h4.z + v4.w*h4.w;
            #pragma unroll
            for (int o = 16; o >= 1; o >>= 1) {
                nu += __shfl_xor_sync(~0u, nu, o);
                vu += __shfl_xor_sync(~0u, vu, o);
                kg += __shfl_xor_sync(~0u, kg, o);
                kw += __shfl_xor_sync(~0u, kw, o);
                vv += __shfl_xor_sync(~0u, vv, o);
                vh += __shfl_xor_sync(~0u, vh, o);
            }
            if (t == 0) {
                // all l-normalizations cancel in wf, wi, and sign(margin)
                double Zc = sZd + (double)vu;          // tr(J SqvS)
                double Ac = sAd + (double)nu;          // tr(J SqqS J^T)  (>=0)
                double Td = sTd + (double)vv;          // tr(SvvS)
                double kgd = kg, kwd = kw, vvd = vv, vhd = vh;
                double Pd = vvd * kgd;                 // l^2 * A_ll
                double ni = Ac * kwd - vhd * Zc;       // sign == sign(margin) == sign(wi)
                const bool first = (l0 == 0);
                int mode = 0; float uwf = 1.f, uwi = 0.f;
                if (first) { mode = 2; }
                else if (ni > 0.0) {
                    mode = 1;
                    double nf  = Pd * Zc - vhd * kwd;
                    double den = Ac * Pd - vhd * vhd;  // >=0 (Cauchy-Schwarz)
                    float rden = __frcp_rn((float)((den == 0.0) ? 1.0 : den));
                    float wfv = (float)nf * rden;
                    if (wfv <= 0.f) {
                        uwf = 0.f;
                        uwi = (float)kwd * __frcp_rn((float)((Pd == 0.0) ? 1.0 : Pd));
                    } else {
                        uwf = wfv;
                        uwi = (float)ni * rden;
                    }
                }
                double Zn, An;
                if (mode == 2)      { Zn = kwd; An = Pd; }
                else if (mode == 1) { double dwf = uwf, dwi = uwi;
                                      Zn = dwf * Zc + dwi * kwd;
                                      An = dwf*dwf*Ac + (2.0*dwf*dwi)*vhd + dwi*dwi*Pd; }
                else                { Zn = Zc; An = Ac; }
                sZd = Zn; sAd = An; sTd = Td;
                outc[l0] = (float)(0.5 * Td - Zn + 0.5 * An)
                         * __frcp_rn((float)(l0 + 1));
                if (outu) outu[l0] = mode ? 1.0f : 0.0f;
                s_mode = mode; s_wf = uwf; s_wi = uwi;
            }
        }
        if (havePf) asm volatile("cp.async.wait_group 0;" ::: "memory");
        __syncthreads();                                    // bar 3

        // ---- Phase D (packed, register-only): conditional J update
        const int mode = s_mode;
        if (mode) {
            if (mode == 2) {
                const u64 vr2 = pack2(v[r]);
                #pragma unroll
                for (int j = 0; j < 8; j++) {
                    ulonglong2 kc = *(const ulonglong2*)&k[c0 + 4 * j];
                    J2[2*j]   = fmul2(vr2, kc.x);
                    J2[2*j+1] = fmul2(vr2, kc.y);
                }
            } else {
                const u64 wf2 = pack2(s_wf);
                const u64 a2  = pack2(s_wi * v[r]);
                #pragma unroll
                for (int j = 0; j < 8; j++) {
                    ulonglong2 kc = *(const ulonglong2*)&k[c0 + 4 * j];
                    J2[2*j]   = ffma2(wf2, J2[2*j],   fmul2(a2, kc.x));
                    J2[2*j+1] = ffma2(wf2, J2[2*j+1], fmul2(a2, kc.y));
                }
            }
        }
        // no barrier needed: J is registers; next Phase A reads the other
        // smem buffer (filled before bar 3)
    }

    // ---- Final: write J (u64 = two adjacent fp32, little-endian)
    if (outJ) {
        #pragma unroll
        for (int p = 0; p < 16; p++)
            *(u64*)&outJ[r * D + c0 + 2 * p] = J2[p];
    }
}

extern "C" void kernel_launch(void* const* d_in, const int* in_sizes, int n_in,
                              void* d_out, int out_size)
{
    const float* q = (const float*)d_in[0];
    const float* k = (const float*)d_in[1];
    const float* v = (const float*)d_in[2];
    gim_kernel<<<1, NTHR>>>(q, k, v, (float*)d_out, out_size);
}